// round 16
// baseline (speedup 1.0000x reference)
#include <cuda_runtime.h>
#include <cuda_fp16.h>

#define BB 256
#define TT 512
#define VV 82
#define EE 256
#define HH 128

typedef unsigned long long u64t;

// x-projection + bias table: P[v][j], j: 0-127 f, 128-255 i, 256-383 o, 384-511 c~
__device__ __align__(16) float d_P[VV * 512];
// repacked recurrent weights: gates g in 0..2: [g][k(0..255)][j(0..127)], then c~: [k(0..127)][j]
__device__ __align__(16) float d_Wpack[3 * 256 * 128 + 128 * 128];
// fp16 mirror (smem tier + L2-streamed tier)
__device__ __align__(16) __half d_W16[3 * 256 * 128 + 128 * 128];

// per A-warp slot partition: 116 slots = 28 reg(fp32) + 52 smem(fp16) + 36 L2(fp16)
#define NREG 28
#define NSM  52

// SMEM layout: fp16 weight cache + fp32 part/state
#define WS_HALF ((7 * NSM + 56) * 128)   // 420 slots x 128 halves = 53760 halves (105 KB)
#define PART_FL (11 * 2 * 128)           // 2816 floats
#define ST_FL   (2 * 256)                // 512 floats
#define SMEM_BYTES (WS_HALF * 2 + (PART_FL + ST_FL) * 4 + 2 * TT)  // 121856

// ---------------------------------------------------------------- helpers
__device__ __forceinline__ u64t dup2(float x) {
    u64t r;
    asm("mov.b64 %0, {%1, %1};" : "=l"(r) : "f"(x));
    return r;
}
__device__ __forceinline__ u64t pk2(float2 v) {
    u64t r;
    asm("mov.b64 %0, {%1, %2};" : "=l"(r) : "f"(v.x), "f"(v.y));
    return r;
}
__device__ __forceinline__ void ffma2(u64t& d, u64t a, u64t b) {
    asm("fma.rn.f32x2 %0, %1, %2, %0;" : "+l"(d) : "l"(a), "l"(b));
}
__device__ __forceinline__ float2 unpk(u64t a) {
    float2 r;
    asm("mov.b64 {%0, %1}, %2;" : "=f"(r.x), "=f"(r.y) : "l"(a));
    return r;
}
__device__ __forceinline__ float sigm(float x) {
    return 1.0f / (1.0f + __expf(-x));
}
__device__ __forceinline__ float tanh_f(float x) {
    float t = __expf(-2.0f * fabsf(x));
    float r = __fdividef(1.0f - t, 1.0f + t);
    return copysignf(r, x);
}

// ---------------------------------------------------------------- merged prep: P table (blocks 0..81) + weight repack
__global__ void __launch_bounds__(512) k_prep(const float* __restrict__ emb,
                       const float* __restrict__ Wf, const float* __restrict__ Wi,
                       const float* __restrict__ Wo, const float* __restrict__ Wc,
                       const float* __restrict__ bf, const float* __restrict__ bi,
                       const float* __restrict__ bo, const float* __restrict__ bc) {
    if (blockIdx.x < VV) {
        __shared__ float se[EE];
        int v = blockIdx.x;
        int j = threadIdx.x;
        if (threadIdx.x < EE) se[threadIdx.x] = emb[v * EE + threadIdx.x];
        __syncthreads();
        const float* w;
        float b;
        if (j < 128)      { w = Wf + j * 512 + 256;         b = bf[j]; }
        else if (j < 256) { w = Wi + (j - 128) * 512 + 256; b = bi[j - 128]; }
        else if (j < 384) { w = Wo + (j - 256) * 512 + 256; b = bo[j - 256]; }
        else              { w = Wc + (j - 384) * 384 + 128; b = bc[j - 384]; }
        float a0 = 0.f, a1 = 0.f, a2 = 0.f, a3 = 0.f;
        float a4 = 0.f, a5 = 0.f, a6 = 0.f, a7 = 0.f;
#pragma unroll
        for (int e = 0; e < EE; e += 8) {
            float4 w0 = __ldg(reinterpret_cast<const float4*>(w + e));
            float4 w1 = __ldg(reinterpret_cast<const float4*>(w + e + 4));
            a0 += w0.x * se[e];
            a1 += w0.y * se[e + 1];
            a2 += w0.z * se[e + 2];
            a3 += w0.w * se[e + 3];
            a4 += w1.x * se[e + 4];
            a5 += w1.y * se[e + 5];
            a6 += w1.z * se[e + 6];
            a7 += w1.w * se[e + 7];
        }
        d_P[v * 512 + j] = b + (((a0 + a1) + (a2 + a3)) + ((a4 + a5) + (a6 + a7)));
    } else {
        int idx = (blockIdx.x - VV) * 512 + threadIdx.x;
        if (idx < 98304) {
            int g = idx >> 15;
            int rem = idx & 32767;
            int k = rem >> 7;
            int j = rem & 127;
            const float* W = (g == 0) ? Wf : (g == 1) ? Wi : Wo;
            float val = W[j * 512 + k];
            d_Wpack[idx] = val;
            d_W16[idx] = __float2half(val);
        } else if (idx < 114688) {
            int r2 = idx - 98304;
            int k = r2 >> 7;
            int j = r2 & 127;
            float val = Wc[j * 384 + k];
            d_Wpack[idx] = val;
            d_W16[idx] = __float2half(val);
        }
    }
}

// ---------------------------------------------------------------- dot kernels (2 rows, 4 j per lane)
template <int NS, int WO>
__device__ __forceinline__ void dot_reg(const u64t (&W)[2 * NREG],
                                        const float* s0r, const float* s1r, u64t* acc) {
#pragma unroll
    for (int k = 0; k < NS; k += 4) {
        float4 s0 = *(const float4*)(s0r + k);
        float4 s1 = *(const float4*)(s1r + k);
        u64t d;
        d = dup2(s0.x); ffma2(acc[0], W[WO + 2*k + 0], d); ffma2(acc[1], W[WO + 2*k + 1], d);
        d = dup2(s1.x); ffma2(acc[2], W[WO + 2*k + 0], d); ffma2(acc[3], W[WO + 2*k + 1], d);
        d = dup2(s0.y); ffma2(acc[0], W[WO + 2*k + 2], d); ffma2(acc[1], W[WO + 2*k + 3], d);
        d = dup2(s1.y); ffma2(acc[2], W[WO + 2*k + 2], d); ffma2(acc[3], W[WO + 2*k + 3], d);
        d = dup2(s0.z); ffma2(acc[0], W[WO + 2*k + 4], d); ffma2(acc[1], W[WO + 2*k + 5], d);
        d = dup2(s1.z); ffma2(acc[2], W[WO + 2*k + 4], d); ffma2(acc[3], W[WO + 2*k + 5], d);
        d = dup2(s0.w); ffma2(acc[0], W[WO + 2*k + 6], d); ffma2(acc[1], W[WO + 2*k + 7], d);
        d = dup2(s1.w); ffma2(acc[2], W[WO + 2*k + 6], d); ffma2(acc[3], W[WO + 2*k + 7], d);
    }
}

// fp16 smem-weight dot: per slot one uint2 (4 halves) per lane, cvt at use
template <int KN>
__device__ __forceinline__ void dot_ptr_h(const __half* __restrict__ wp,
                                          const float* s0r, const float* s1r, u64t* acc) {
#pragma unroll
    for (int k = 0; k < KN; k += 4) {
        float4 s0 = *(const float4*)(s0r + k);
        float4 s1 = *(const float4*)(s1r + k);
        uint2 h0 = *(const uint2*)(wp + (k + 0) * 128);
        uint2 h1 = *(const uint2*)(wp + (k + 1) * 128);
        uint2 h2 = *(const uint2*)(wp + (k + 2) * 128);
        uint2 h3 = *(const uint2*)(wp + (k + 3) * 128);
        u64t wa, wb, d;
        wa = pk2(__half22float2(*reinterpret_cast<const __half2*>(&h0.x)));
        wb = pk2(__half22float2(*reinterpret_cast<const __half2*>(&h0.y)));
        d = dup2(s0.x); ffma2(acc[0], wa, d); ffma2(acc[1], wb, d);
        d = dup2(s1.x); ffma2(acc[2], wa, d); ffma2(acc[3], wb, d);
        wa = pk2(__half22float2(*reinterpret_cast<const __half2*>(&h1.x)));
        wb = pk2(__half22float2(*reinterpret_cast<const __half2*>(&h1.y)));
        d = dup2(s0.y); ffma2(acc[0], wa, d); ffma2(acc[1], wb, d);
        d = dup2(s1.y); ffma2(acc[2], wa, d); ffma2(acc[3], wb, d);
        wa = pk2(__half22float2(*reinterpret_cast<const __half2*>(&h2.x)));
        wb = pk2(__half22float2(*reinterpret_cast<const __half2*>(&h2.y)));
        d = dup2(s0.z); ffma2(acc[0], wa, d); ffma2(acc[1], wb, d);
        d = dup2(s1.z); ffma2(acc[2], wa, d); ffma2(acc[3], wb, d);
        wa = pk2(__half22float2(*reinterpret_cast<const __half2*>(&h3.x)));
        wb = pk2(__half22float2(*reinterpret_cast<const __half2*>(&h3.y)));
        d = dup2(s0.w); ffma2(acc[0], wa, d); ffma2(acc[1], wb, d);
        d = dup2(s1.w); ffma2(acc[2], wa, d); ffma2(acc[3], wb, d);
    }
}

// consume an fp16 L2-prefetched batch: each uint2 = 4 halves (j0..j3) of one slot
template <int NB>
__device__ __forceinline__ void consumeH(const uint2* L,
                                         const float* s0r, const float* s1r, u64t* acc) {
#pragma unroll
    for (int k = 0; k < NB; k += 4) {
        float4 s0 = *(const float4*)(s0r + k);
        float4 s1 = *(const float4*)(s1r + k);
#pragma unroll
        for (int kk = 0; kk < 4; kk++) {
            __half2 ha = *reinterpret_cast<const __half2*>(&L[k + kk].x);
            __half2 hb = *reinterpret_cast<const __half2*>(&L[k + kk].y);
            u64t wa = pk2(__half22float2(ha));
            u64t wb = pk2(__half22float2(hb));
            float sv0 = (kk == 0) ? s0.x : (kk == 1) ? s0.y : (kk == 2) ? s0.z : s0.w;
            float sv1 = (kk == 0) ? s1.x : (kk == 1) ? s1.y : (kk == 2) ? s1.z : s1.w;
            u64t d;
            d = dup2(sv0); ffma2(acc[0], wa, d); ffma2(acc[1], wb, d);
            d = dup2(sv1); ffma2(acc[2], wa, d); ffma2(acc[3], wb, d);
        }
    }
}

__device__ __forceinline__ void store_part(float* part, int pbuf, int jb, const u64t* acc) {
    float2 a = unpk(acc[0]), b = unpk(acc[1]);
    *(float4*)(part + (pbuf * 2 + 0) * 128 + jb) = make_float4(a.x, a.y, b.x, b.y);
    a = unpk(acc[2]); b = unpk(acc[3]);
    *(float4*)(part + (pbuf * 2 + 1) * 128 + jb) = make_float4(a.x, a.y, b.x, b.y);
}

// ---------------------------------------------------------------- recurrent kernel: 128 CTAs x 256 thr, 2 rows/CTA
// Warp roles (k-slot partition of the 896 total k-slots):
//   w0: f[0,116)   w1: f[116,232)   w2: i[0,116)  w3: i[116,232)
//   w4: o[0,116)   w5: o[116,232)   w6: c[0,116)
//   w7: c[116,128) + f[232,256) + i[232,256) + o[232,256)
// A-warps: rel [0,28) reg fp32 + [28,80) smem fp16 + [80,116) L2-streamed fp16.
// w7: reg = c12 + f[232,248)16;  smem fp16 = f[248,256)8 + i24 + o24.
__global__ void __launch_bounds__(256, 1) k_recur(const int* __restrict__ reviews,
                                                  const float* __restrict__ Wcls,
                                                  const float* __restrict__ bcls,
                                                  float* __restrict__ out) {
    extern __shared__ __align__(16) char smc[];
    __half* wsh = (__half*)smc;                          // [420 slots][128] fp16
    float* part = (float*)(smc + WS_HALF * 2);           // [11][2][128]
    float* st   = part + PART_FL;                        // [2][256]: c(0:128)|h(128:256)
    unsigned char* tok = (unsigned char*)(st + ST_FL);   // [2][512]

    const int tid = threadIdx.x;
    const int w = tid >> 5, lane = tid & 31;
    const int jb = 4 * lane;
    const int b0 = blockIdx.x * 2;

    // ---- per-warp config (A-warps)
    const int g = w >> 1;                  // w6 -> 3 (c~)
    const int k0 = (w & 1) * 116;
    const int gbase = (g < 3) ? g * 32768 : 98304;
    const int wr_off = gbase + k0 * 128;
    const int sbase = ((g < 3) ? 0 : 128) + k0;
    const int pbuf = g * 3 + (w & 1);

    // ---- fill SMEM weight regions (fp16, from d_W16)
    if (w < 7) {
        const __half* src = d_W16 + wr_off + NREG * 128 + jb;
        __half* dst = wsh + w * (NSM * 128) + jb;
        for (int s = 0; s < NSM; s++)
            *(uint2*)(dst + s * 128) = *(const uint2*)(src + s * 128);
    } else {
        __half* dst = wsh + 7 * (NSM * 128) + jb;
        const __half* sf = d_W16 + 248 * 128 + jb;           // f[248,256): 8
        const __half* si = d_W16 + 32768 + 232 * 128 + jb;   // i[232,256): 24
        const __half* so = d_W16 + 65536 + 232 * 128 + jb;   // o[232,256): 24
        for (int s = 0; s < 8; s++)
            *(uint2*)(dst + s * 128) = *(const uint2*)(sf + s * 128);
        for (int s = 0; s < 24; s++) {
            *(uint2*)(dst + (8 + s) * 128)  = *(const uint2*)(si + s * 128);
            *(uint2*)(dst + (32 + s) * 128) = *(const uint2*)(so + s * 128);
        }
    }

    // ---- load register weights (28 slots = 56 u64 = 112 regs, fp32)
    u64t Wr[2 * NREG];
    if (w < 7) {
        const float* src = d_Wpack + wr_off + jb;
#pragma unroll
        for (int s = 0; s < NREG; s++) {
            ulonglong2 v = *(const ulonglong2*)(src + s * 128);
            Wr[2 * s] = v.x; Wr[2 * s + 1] = v.y;
        }
    } else {
        const float* sc = d_Wpack + 98304 + 116 * 128 + jb;   // c[116,128): 12 slots
        const float* sf = d_Wpack + 232 * 128 + jb;           // f[232,248): 16 slots
#pragma unroll
        for (int s = 0; s < 12; s++) {
            ulonglong2 v = *(const ulonglong2*)(sc + s * 128);
            Wr[2 * s] = v.x; Wr[2 * s + 1] = v.y;
        }
#pragma unroll
        for (int s = 0; s < 16; s++) {
            ulonglong2 v = *(const ulonglong2*)(sf + s * 128);
            Wr[24 + 2 * s] = v.x; Wr[24 + 2 * s + 1] = v.y;
        }
    }

    // ---- tokens + state init
    for (int i = tid; i < 2 * TT; i += 256) {
        int r = i >> 9, t = i & (TT - 1);
        tok[i] = (unsigned char)reviews[(size_t)(b0 + r) * TT + t];
    }
    for (int i = tid; i < ST_FL; i += 256) st[i] = 0.0f;
    __syncthreads();

    const float* st0 = st;
    const float* st1 = st + 256;
    const __half* wsm_h = wsh + w * (NSM * 128) + jb;           // A: slots [28,80) fp16
    const __half* wl2h  = d_W16 + wr_off + 80 * 128 + jb;       // A: slots [80,116) fp16
    const __half* wsB_h = wsh + 7 * (NSM * 128) + jb;           // w7 region fp16

    // update-role constants
    const int ur = tid >> 7;          // row 0/1
    const int uj = tid & 127;         // j
    float* str = st + ur * 256;

    const size_t G = (size_t)TT * BB * HH;
    float* const outf = out + BB * VV;

    for (int t = 0; t < TT; t++) {
        // P prefetch (consumed after the barrier)
        int v = tok[(ur << 9) + t];
        const float* Pb = d_P + v * 512 + uj;
        float Pf = __ldg(Pb);
        float Pi = __ldg(Pb + 128);
        float Po = __ldg(Pb + 256);
        float Pc = __ldg(Pb + 384);

        if (w < 7) {
            u64t acc[4] = {0, 0, 0, 0};
            uint2 L[8];
            const float* sb0 = st0 + sbase;
            const float* sb1 = st1 + sbase;
#pragma unroll
            for (int s = 0; s < 8; s++) L[s] = *(const uint2*)(wl2h + s * 128);
            dot_reg<NREG, 0>(Wr, sb0, sb1, acc);
            consumeH<8>(L, sb0 + 80, sb1 + 80, acc);
#pragma unroll
            for (int s = 0; s < 8; s++) L[s] = *(const uint2*)(wl2h + (8 + s) * 128);
            dot_ptr_h<16>(wsm_h, sb0 + 28, sb1 + 28, acc);
            consumeH<8>(L, sb0 + 88, sb1 + 88, acc);
#pragma unroll
            for (int s = 0; s < 8; s++) L[s] = *(const uint2*)(wl2h + (16 + s) * 128);
            dot_ptr_h<16>(wsm_h + 16 * 128, sb0 + 44, sb1 + 44, acc);
            consumeH<8>(L, sb0 + 96, sb1 + 96, acc);
#pragma unroll
            for (int s = 0; s < 8; s++) L[s] = *(const uint2*)(wl2h + (24 + s) * 128);
            dot_ptr_h<12>(wsm_h + 32 * 128, sb0 + 60, sb1 + 60, acc);
            consumeH<8>(L, sb0 + 104, sb1 + 104, acc);
#pragma unroll
            for (int s = 0; s < 4; s++) L[s] = *(const uint2*)(wl2h + (32 + s) * 128);
            dot_ptr_h<8>(wsm_h + 44 * 128, sb0 + 72, sb1 + 72, acc);
            consumeH<4>(L, sb0 + 112, sb1 + 112, acc);
            store_part(part, pbuf, jb, acc);
        } else {
            u64t acc[4];
            // c~[116,128): reg, state 244
            acc[0] = acc[1] = acc[2] = acc[3] = 0;
            dot_reg<12, 0>(Wr, st0 + 244, st1 + 244, acc);
            store_part(part, 10, jb, acc);
            // f[232,256): reg 16 (state 232) + smem fp16 8 (state 248)
            acc[0] = acc[1] = acc[2] = acc[3] = 0;
            dot_reg<16, 24>(Wr, st0 + 232, st1 + 232, acc);
            dot_ptr_h<8>(wsB_h, st0 + 248, st1 + 248, acc);
            store_part(part, 2, jb, acc);
            // i[232,256): smem fp16
            acc[0] = acc[1] = acc[2] = acc[3] = 0;
            dot_ptr_h<24>(wsB_h + 8 * 128, st0 + 232, st1 + 232, acc);
            store_part(part, 5, jb, acc);
            // o[232,256): smem fp16
            acc[0] = acc[1] = acc[2] = acc[3] = 0;
            dot_ptr_h<24>(wsB_h + 32 * 128, st0 + 232, st1 + 232, acc);
            store_part(part, 8, jb, acc);
        }
        __syncthreads();

        // update phase: thread owns (row ur, col uj)
        {
            const float* p = part + ur * 128 + uj;
            float pf = p[0 * 256] + p[1 * 256] + p[2 * 256] + Pf;
            float pi = p[3 * 256] + p[4 * 256] + p[5 * 256] + Pi;
            float po = p[6 * 256] + p[7 * 256] + p[8 * 256] + Po;
            float pc = p[9 * 256] + p[10 * 256] + Pc;

            float f  = sigm(pf);
            float ii = sigm(pi);
            float o  = sigm(po);
            float ct = tanh_f(pc);

            float c  = str[uj];
            float cn = f * c + ii * ct;
            float hn = o * tanh_f(cn);
            str[uj] = cn;
            str[128 + uj] = hn;

            size_t ob = ((size_t)t * BB + b0 + ur) * HH + uj;
            outf[ob]         = f;
            outf[G + ob]     = ii;
            outf[2 * G + ob] = o;
        }
        __syncthreads();
    }

    // classifier on final h
    for (int idx = tid; idx < 2 * VV; idx += 256) {
        int r = idx / VV, v2 = idx % VV;
        const float* hr = st + r * 256 + 128;
        const float* wr = Wcls + v2 * HH;
        float a0 = 0.f, a1 = 0.f, a2 = 0.f, a3 = 0.f;
#pragma unroll 8
        for (int j = 0; j < HH; j += 4) {
            float4 wv = __ldg(reinterpret_cast<const float4*>(wr + j));
            a0 += wv.x * hr[j];
            a1 += wv.y * hr[j + 1];
            a2 += wv.z * hr[j + 2];
            a3 += wv.w * hr[j + 3];
        }
        out[(size_t)(b0 + r) * VV + v2] = __ldg(bcls + v2) + ((a0 + a1) + (a2 + a3));
    }
}

// ---------------------------------------------------------------- launch
extern "C" void kernel_launch(void* const* d_in, const int* in_sizes, int n_in,
                              void* d_out, int out_size) {
    (void)in_sizes; (void)n_in; (void)out_size;
    const int*   reviews = (const int*)d_in[0];
    const float* emb   = (const float*)d_in[1];
    const float* Wf    = (const float*)d_in[2];
    const float* Wi    = (const float*)d_in[3];
    const float* Wo    = (const float*)d_in[4];
    const float* Wc    = (const float*)d_in[5];
    const float* bf    = (const float*)d_in[6];
    const float* bi    = (const float*)d_in[7];
    const float* bo    = (const float*)d_in[8];
    const float* bc    = (const float*)d_in[9];
    const float* Wcls  = (const float*)d_in[10];
    const float* bcls  = (const float*)d_in[11];
    float* out = (float*)d_out;

    cudaFuncSetAttribute(k_recur, cudaFuncAttributeMaxDynamicSharedMemorySize, SMEM_BYTES);

    k_prep<<<VV + 224, 512>>>(emb, Wf, Wi, Wo, Wc, bf, bi, bo, bc);
    k_recur<<<BB / 2, 256, SMEM_BYTES>>>(reviews, Wcls, bcls, out);
}

// round 17
// speedup vs baseline: 1.1220x; 1.1220x over previous
#include <cuda_runtime.h>
#include <cuda_bf16.h>

#define BB 256
#define TT 512
#define VV 82
#define EE 256
#define HH 128

typedef unsigned long long u64t;

// x-projection + bias table: P[v][j], j: 0-127 f, 128-255 i, 256-383 o, 384-511 c~
__device__ __align__(16) float d_P[VV * 512];
// repacked recurrent weights fp32 (register tier): g in 0..2: [g][k][j], then c~
__device__ __align__(16) float d_Wpack[3 * 256 * 128 + 128 * 128];
// bf16 PAIR-PACKED mirror (smem + L2 tiers):
// index = region_base + (k>>1)*256 + (j>>2)*8 + (k&1)*4 + (j&3)
__device__ __align__(16) __nv_bfloat16 d_Wbp[3 * 256 * 128 + 128 * 128];

// per A-warp slot partition: 116 slots = 28 reg(fp32) + 52 smem(bf16) + 36 L2(bf16)
#define NREG 28
#define NSM  52

// SMEM layout: bf16 packed weight cache + fp32 part/state
#define WS_HALF (7 * 26 * 256 + 28 * 256)   // 53760 bf16 (105 KB): 7 warps x 26 pairs + w7 28 pairs
#define PART_FL (11 * 2 * 128)              // 2816 floats
#define ST_FL   (2 * 256)                   // 512 floats
#define SMEM_BYTES (WS_HALF * 2 + (PART_FL + ST_FL) * 4 + 2 * TT)  // 121856

// ---------------------------------------------------------------- helpers
__device__ __forceinline__ u64t dup2(float x) {
    u64t r;
    asm("mov.b64 %0, {%1, %1};" : "=l"(r) : "f"(x));
    return r;
}
// expand 2 packed bf16 (in one 32b word) to an f32x2 pair via alu-pipe shifts
__device__ __forceinline__ u64t bfx2(unsigned h) {
    u64t r;
    asm("{\n\t"
        ".reg .b32 lo, hi;\n\t"
        "shl.b32 lo, %1, 16;\n\t"
        "and.b32 hi, %1, 0xFFFF0000;\n\t"
        "mov.b64 %0, {lo, hi};\n\t"
        "}" : "=l"(r) : "r"(h));
    return r;
}
__device__ __forceinline__ void ffma2(u64t& d, u64t a, u64t b) {
    asm("fma.rn.f32x2 %0, %1, %2, %0;" : "+l"(d) : "l"(a), "l"(b));
}
__device__ __forceinline__ float2 unpk(u64t a) {
    float2 r;
    asm("mov.b64 {%0, %1}, %2;" : "=f"(r.x), "=f"(r.y) : "l"(a));
    return r;
}
__device__ __forceinline__ float sigm(float x) {
    return 1.0f / (1.0f + __expf(-x));
}
__device__ __forceinline__ float tanh_f(float x) {
    float t = __expf(-2.0f * fabsf(x));
    float r = __fdividef(1.0f - t, 1.0f + t);
    return copysignf(r, x);
}

// ---------------------------------------------------------------- merged prep: P table (blocks 0..81) + weight repack
__global__ void __launch_bounds__(512) k_prep(const float* __restrict__ emb,
                       const float* __restrict__ Wf, const float* __restrict__ Wi,
                       const float* __restrict__ Wo, const float* __restrict__ Wc,
                       const float* __restrict__ bf, const float* __restrict__ bi,
                       const float* __restrict__ bo, const float* __restrict__ bc) {
    if (blockIdx.x < VV) {
        __shared__ float se[EE];
        int v = blockIdx.x;
        int j = threadIdx.x;
        if (threadIdx.x < EE) se[threadIdx.x] = emb[v * EE + threadIdx.x];
        __syncthreads();
        const float* w;
        float b;
        if (j < 128)      { w = Wf + j * 512 + 256;         b = bf[j]; }
        else if (j < 256) { w = Wi + (j - 128) * 512 + 256; b = bi[j - 128]; }
        else if (j < 384) { w = Wo + (j - 256) * 512 + 256; b = bo[j - 256]; }
        else              { w = Wc + (j - 384) * 384 + 128; b = bc[j - 384]; }
        float a0 = 0.f, a1 = 0.f, a2 = 0.f, a3 = 0.f;
        float a4 = 0.f, a5 = 0.f, a6 = 0.f, a7 = 0.f;
#pragma unroll
        for (int e = 0; e < EE; e += 8) {
            float4 w0 = __ldg(reinterpret_cast<const float4*>(w + e));
            float4 w1 = __ldg(reinterpret_cast<const float4*>(w + e + 4));
            a0 += w0.x * se[e];
            a1 += w0.y * se[e + 1];
            a2 += w0.z * se[e + 2];
            a3 += w0.w * se[e + 3];
            a4 += w1.x * se[e + 4];
            a5 += w1.y * se[e + 5];
            a6 += w1.z * se[e + 6];
            a7 += w1.w * se[e + 7];
        }
        d_P[v * 512 + j] = b + (((a0 + a1) + (a2 + a3)) + ((a4 + a5) + (a6 + a7)));
    } else {
        int idx = (blockIdx.x - VV) * 512 + threadIdx.x;
        if (idx < 98304) {
            int g = idx >> 15;
            int rem = idx & 32767;
            int k = rem >> 7;
            int j = rem & 127;
            const float* W = (g == 0) ? Wf : (g == 1) ? Wi : Wo;
            float val = W[j * 512 + k];
            d_Wpack[idx] = val;
            d_Wbp[g * 32768 + ((k >> 1) << 8) + ((j >> 2) << 3) + ((k & 1) << 2) + (j & 3)]
                = __float2bfloat16(val);
        } else if (idx < 114688) {
            int r2 = idx - 98304;
            int k = r2 >> 7;
            int j = r2 & 127;
            float val = Wc[j * 384 + k];
            d_Wpack[idx] = val;
            d_Wbp[98304 + ((k >> 1) << 8) + ((j >> 2) << 3) + ((k & 1) << 2) + (j & 3)]
                = __float2bfloat16(val);
        }
    }
}

// ---------------------------------------------------------------- dot kernels (2 rows, 4 j per lane)
template <int NS, int WO>
__device__ __forceinline__ void dot_reg(const u64t (&W)[2 * NREG],
                                        const float* s0r, const float* s1r, u64t* acc) {
#pragma unroll
    for (int k = 0; k < NS; k += 4) {
        float4 s0 = *(const float4*)(s0r + k);
        float4 s1 = *(const float4*)(s1r + k);
        u64t d;
        d = dup2(s0.x); ffma2(acc[0], W[WO + 2*k + 0], d); ffma2(acc[1], W[WO + 2*k + 1], d);
        d = dup2(s1.x); ffma2(acc[2], W[WO + 2*k + 0], d); ffma2(acc[3], W[WO + 2*k + 1], d);
        d = dup2(s0.y); ffma2(acc[0], W[WO + 2*k + 2], d); ffma2(acc[1], W[WO + 2*k + 3], d);
        d = dup2(s1.y); ffma2(acc[2], W[WO + 2*k + 2], d); ffma2(acc[3], W[WO + 2*k + 3], d);
        d = dup2(s0.z); ffma2(acc[0], W[WO + 2*k + 4], d); ffma2(acc[1], W[WO + 2*k + 5], d);
        d = dup2(s1.z); ffma2(acc[2], W[WO + 2*k + 4], d); ffma2(acc[3], W[WO + 2*k + 5], d);
        d = dup2(s0.w); ffma2(acc[0], W[WO + 2*k + 6], d); ffma2(acc[1], W[WO + 2*k + 7], d);
        d = dup2(s1.w); ffma2(acc[2], W[WO + 2*k + 6], d); ffma2(acc[3], W[WO + 2*k + 7], d);
    }
}

// paired bf16 dot: one uint4 per lane covers 2 slots (4 j each). wp already +lane*8.
template <int KN>
__device__ __forceinline__ void dot_pair(const __nv_bfloat16* __restrict__ wp,
                                         const float* s0r, const float* s1r, u64t* acc) {
#pragma unroll
    for (int k = 0; k < KN; k += 4) {
        float4 s0 = *(const float4*)(s0r + k);
        float4 s1 = *(const float4*)(s1r + k);
        uint4 A = *(const uint4*)(wp + (k >> 1) * 256);
        uint4 B = *(const uint4*)(wp + (k >> 1) * 256 + 256);
        u64t wa, wb, d;
        wa = bfx2(A.x); wb = bfx2(A.y);
        d = dup2(s0.x); ffma2(acc[0], wa, d); ffma2(acc[1], wb, d);
        d = dup2(s1.x); ffma2(acc[2], wa, d); ffma2(acc[3], wb, d);
        wa = bfx2(A.z); wb = bfx2(A.w);
        d = dup2(s0.y); ffma2(acc[0], wa, d); ffma2(acc[1], wb, d);
        d = dup2(s1.y); ffma2(acc[2], wa, d); ffma2(acc[3], wb, d);
        wa = bfx2(B.x); wb = bfx2(B.y);
        d = dup2(s0.z); ffma2(acc[0], wa, d); ffma2(acc[1], wb, d);
        d = dup2(s1.z); ffma2(acc[2], wa, d); ffma2(acc[3], wb, d);
        wa = bfx2(B.z); wb = bfx2(B.w);
        d = dup2(s0.w); ffma2(acc[0], wa, d); ffma2(acc[1], wb, d);
        d = dup2(s1.w); ffma2(acc[2], wa, d); ffma2(acc[3], wb, d);
    }
}

// consume prefetched bf16 pairs held in registers (NB slots, NB/2 pairs in L)
template <int NB>
__device__ __forceinline__ void consumeP(const uint4* L,
                                         const float* s0r, const float* s1r, u64t* acc) {
#pragma unroll
    for (int k = 0; k < NB; k += 4) {
        float4 s0 = *(const float4*)(s0r + k);
        float4 s1 = *(const float4*)(s1r + k);
        uint4 A = L[k >> 1];
        uint4 B = L[(k >> 1) + 1];
        u64t wa, wb, d;
        wa = bfx2(A.x); wb = bfx2(A.y);
        d = dup2(s0.x); ffma2(acc[0], wa, d); ffma2(acc[1], wb, d);
        d = dup2(s1.x); ffma2(acc[2], wa, d); ffma2(acc[3], wb, d);
        wa = bfx2(A.z); wb = bfx2(A.w);
        d = dup2(s0.y); ffma2(acc[0], wa, d); ffma2(acc[1], wb, d);
        d = dup2(s1.y); ffma2(acc[2], wa, d); ffma2(acc[3], wb, d);
        wa = bfx2(B.x); wb = bfx2(B.y);
        d = dup2(s0.z); ffma2(acc[0], wa, d); ffma2(acc[1], wb, d);
        d = dup2(s1.z); ffma2(acc[2], wa, d); ffma2(acc[3], wb, d);
        wa = bfx2(B.z); wb = bfx2(B.w);
        d = dup2(s0.w); ffma2(acc[0], wa, d); ffma2(acc[1], wb, d);
        d = dup2(s1.w); ffma2(acc[2], wa, d); ffma2(acc[3], wb, d);
    }
}

__device__ __forceinline__ void store_part(float* part, int pbuf, int jb, const u64t* acc) {
    float2 a = unpk(acc[0]), b = unpk(acc[1]);
    *(float4*)(part + (pbuf * 2 + 0) * 128 + jb) = make_float4(a.x, a.y, b.x, b.y);
    a = unpk(acc[2]); b = unpk(acc[3]);
    *(float4*)(part + (pbuf * 2 + 1) * 128 + jb) = make_float4(a.x, a.y, b.x, b.y);
}

// ---------------------------------------------------------------- recurrent kernel: 128 CTAs x 256 thr, 2 rows/CTA
// Warp roles (k-slot partition of the 896 total k-slots):
//   w0: f[0,116)   w1: f[116,232)   w2: i[0,116)  w3: i[116,232)
//   w4: o[0,116)   w5: o[116,232)   w6: c[0,116)
//   w7: c[116,128) + f[232,256) + i[232,256) + o[232,256)
// A-warps: rel [0,28) reg fp32 + [28,80) smem bf16-pairs + [80,116) L2-streamed bf16-pairs.
// w7: reg = c12 + f[232,248)16;  smem bf16 = f[248,256)4p + i 12p + o 12p.
__global__ void __launch_bounds__(256, 1) k_recur(const int* __restrict__ reviews,
                                                  const float* __restrict__ Wcls,
                                                  const float* __restrict__ bcls,
                                                  float* __restrict__ out) {
    extern __shared__ __align__(16) char smc[];
    __nv_bfloat16* wsh = (__nv_bfloat16*)smc;            // packed pairs
    float* part = (float*)(smc + WS_HALF * 2);           // [11][2][128]
    float* st   = part + PART_FL;                        // [2][256]: c(0:128)|h(128:256)
    unsigned char* tok = (unsigned char*)(st + ST_FL);   // [2][512]

    const int tid = threadIdx.x;
    const int w = tid >> 5, lane = tid & 31;
    const int jb = 4 * lane;
    const int l8 = lane * 8;
    const int b0 = blockIdx.x * 2;

    // ---- per-warp config (A-warps)
    const int g = w >> 1;                  // w6 -> 3 (c~)
    const int k0 = (w & 1) * 116;
    const int gbase = (g < 3) ? g * 32768 : 98304;
    const int wr_off = gbase + k0 * 128;
    const int sbase = ((g < 3) ? 0 : 128) + k0;
    const int pbuf = g * 3 + (w & 1);

    // ---- fill SMEM weight regions (bf16 pairs from d_Wbp)
    if (w < 7) {
        const __nv_bfloat16* src = d_Wbp + gbase + ((k0 + NREG) >> 1) * 256 + l8;
        __nv_bfloat16* dst = wsh + w * (26 * 256) + l8;
        for (int s = 0; s < 26; s++)
            *(uint4*)(dst + s * 256) = *(const uint4*)(src + s * 256);
    } else {
        __nv_bfloat16* dst = wsh + 7 * (26 * 256) + l8;
        const __nv_bfloat16* sf = d_Wbp + (248 >> 1) * 256 + l8;            // f pairs 124..127
        const __nv_bfloat16* si = d_Wbp + 32768 + (232 >> 1) * 256 + l8;    // i pairs 116..127
        const __nv_bfloat16* so = d_Wbp + 65536 + (232 >> 1) * 256 + l8;    // o pairs 116..127
        for (int s = 0; s < 4; s++)
            *(uint4*)(dst + s * 256) = *(const uint4*)(sf + s * 256);
        for (int s = 0; s < 12; s++) {
            *(uint4*)(dst + (4 + s) * 256)  = *(const uint4*)(si + s * 256);
            *(uint4*)(dst + (16 + s) * 256) = *(const uint4*)(so + s * 256);
        }
    }

    // ---- load register weights (28 slots = 56 u64 = 112 regs, fp32)
    u64t Wr[2 * NREG];
    if (w < 7) {
        const float* src = d_Wpack + wr_off + jb;
#pragma unroll
        for (int s = 0; s < NREG; s++) {
            ulonglong2 v = *(const ulonglong2*)(src + s * 128);
            Wr[2 * s] = v.x; Wr[2 * s + 1] = v.y;
        }
    } else {
        const float* sc = d_Wpack + 98304 + 116 * 128 + jb;   // c[116,128): 12 slots
        const float* sf = d_Wpack + 232 * 128 + jb;           // f[232,248): 16 slots
#pragma unroll
        for (int s = 0; s < 12; s++) {
            ulonglong2 v = *(const ulonglong2*)(sc + s * 128);
            Wr[2 * s] = v.x; Wr[2 * s + 1] = v.y;
        }
#pragma unroll
        for (int s = 0; s < 16; s++) {
            ulonglong2 v = *(const ulonglong2*)(sf + s * 128);
            Wr[24 + 2 * s] = v.x; Wr[24 + 2 * s + 1] = v.y;
        }
    }

    // ---- tokens + state init
    for (int i = tid; i < 2 * TT; i += 256) {
        int r = i >> 9, t = i & (TT - 1);
        tok[i] = (unsigned char)reviews[(size_t)(b0 + r) * TT + t];
    }
    for (int i = tid; i < ST_FL; i += 256) st[i] = 0.0f;
    __syncthreads();

    const float* st0 = st;
    const float* st1 = st + 256;
    const __nv_bfloat16* wsm_p = wsh + w * (26 * 256) + l8;                      // A smem pairs
    const __nv_bfloat16* wl2_p = d_Wbp + gbase + ((k0 + 80) >> 1) * 256 + l8;    // A L2 pairs
    const __nv_bfloat16* ws7   = wsh + 7 * (26 * 256) + l8;                      // w7 region

    // update-role constants
    const int ur = tid >> 7;          // row 0/1
    const int uj = tid & 127;         // j
    float* str = st + ur * 256;

    const size_t G = (size_t)TT * BB * HH;
    float* const outf = out + BB * VV;

    for (int t = 0; t < TT; t++) {
        // P prefetch (consumed after the barrier)
        int v = tok[(ur << 9) + t];
        const float* Pb = d_P + v * 512 + uj;
        float Pf = __ldg(Pb);
        float Pi = __ldg(Pb + 128);
        float Po = __ldg(Pb + 256);
        float Pc = __ldg(Pb + 384);

        if (w < 7) {
            u64t acc[4] = {0, 0, 0, 0};
            uint4 L[4];
            const float* sb0 = st0 + sbase;
            const float* sb1 = st1 + sbase;
#pragma unroll
            for (int s = 0; s < 4; s++) L[s] = *(const uint4*)(wl2_p + s * 256);
            dot_reg<NREG, 0>(Wr, sb0, sb1, acc);
            consumeP<8>(L, sb0 + 80, sb1 + 80, acc);
#pragma unroll
            for (int s = 0; s < 4; s++) L[s] = *(const uint4*)(wl2_p + (4 + s) * 256);
            dot_pair<16>(wsm_p, sb0 + 28, sb1 + 28, acc);
            consumeP<8>(L, sb0 + 88, sb1 + 88, acc);
#pragma unroll
            for (int s = 0; s < 4; s++) L[s] = *(const uint4*)(wl2_p + (8 + s) * 256);
            dot_pair<16>(wsm_p + 8 * 256, sb0 + 44, sb1 + 44, acc);
            consumeP<8>(L, sb0 + 96, sb1 + 96, acc);
#pragma unroll
            for (int s = 0; s < 4; s++) L[s] = *(const uint4*)(wl2_p + (12 + s) * 256);
            dot_pair<12>(wsm_p + 16 * 256, sb0 + 60, sb1 + 60, acc);
            consumeP<8>(L, sb0 + 104, sb1 + 104, acc);
#pragma unroll
            for (int s = 0; s < 2; s++) L[s] = *(const uint4*)(wl2_p + (16 + s) * 256);
            dot_pair<8>(wsm_p + 22 * 256, sb0 + 72, sb1 + 72, acc);
            consumeP<4>(L, sb0 + 112, sb1 + 112, acc);
            store_part(part, pbuf, jb, acc);
        } else {
            u64t acc[4];
            // c~[116,128): reg, state 244
            acc[0] = acc[1] = acc[2] = acc[3] = 0;
            dot_reg<12, 0>(Wr, st0 + 244, st1 + 244, acc);
            store_part(part, 10, jb, acc);
            // f[232,256): reg 16 (state 232) + smem bf16 8 (state 248)
            acc[0] = acc[1] = acc[2] = acc[3] = 0;
            dot_reg<16, 24>(Wr, st0 + 232, st1 + 232, acc);
            dot_pair<8>(ws7, st0 + 248, st1 + 248, acc);
            store_part(part, 2, jb, acc);
            // i[232,256): smem bf16
            acc[0] = acc[1] = acc[2] = acc[3] = 0;
            dot_pair<24>(ws7 + 4 * 256, st0 + 232, st1 + 232, acc);
            store_part(part, 5, jb, acc);
            // o[232,256): smem bf16
            acc[0] = acc[1] = acc[2] = acc[3] = 0;
            dot_pair<24>(ws7 + 16 * 256, st0 + 232, st1 + 232, acc);
            store_part(part, 8, jb, acc);
        }
        __syncthreads();

        // update phase: thread owns (row ur, col uj)
        {
            const float* p = part + ur * 128 + uj;
            float pf = p[0 * 256] + p[1 * 256] + p[2 * 256] + Pf;
            float pi = p[3 * 256] + p[4 * 256] + p[5 * 256] + Pi;
            float po = p[6 * 256] + p[7 * 256] + p[8 * 256] + Po;
            float pc = p[9 * 256] + p[10 * 256] + Pc;

            float f  = sigm(pf);
            float ii = sigm(pi);
            float o  = sigm(po);
            float ct = tanh_f(pc);

            float c  = str[uj];
            float cn = f * c + ii * ct;
            float hn = o * tanh_f(cn);
            str[uj] = cn;
            str[128 + uj] = hn;

            size_t ob = ((size_t)t * BB + b0 + ur) * HH + uj;
            outf[ob]         = f;
            outf[G + ob]     = ii;
            outf[2 * G + ob] = o;
        }
        __syncthreads();
    }

    // classifier on final h
    for (int idx = tid; idx < 2 * VV; idx += 256) {
        int r = idx / VV, v2 = idx % VV;
        const float* hr = st + r * 256 + 128;
        const float* wr = Wcls + v2 * HH;
        float a0 = 0.f, a1 = 0.f, a2 = 0.f, a3 = 0.f;
#pragma unroll 8
        for (int j = 0; j < HH; j += 4) {
            float4 wv = __ldg(reinterpret_cast<const float4*>(wr + j));
            a0 += wv.x * hr[j];
            a1 += wv.y * hr[j + 1];
            a2 += wv.z * hr[j + 2];
            a3 += wv.w * hr[j + 3];
        }
        out[(size_t)(b0 + r) * VV + v2] = __ldg(bcls + v2) + ((a0 + a1) + (a2 + a3));
    }
}

// ---------------------------------------------------------------- launch
extern "C" void kernel_launch(void* const* d_in, const int* in_sizes, int n_in,
                              void* d_out, int out_size) {
    (void)in_sizes; (void)n_in; (void)out_size;
    const int*   reviews = (const int*)d_in[0];
    const float* emb   = (const float*)d_in[1];
    const float* Wf    = (const float*)d_in[2];
    const float* Wi    = (const float*)d_in[3];
    const float* Wo    = (const float*)d_in[4];
    const float* Wc    = (const float*)d_in[5];
    const float* bf    = (const float*)d_in[6];
    const float* bi    = (const float*)d_in[7];
    const float* bo    = (const float*)d_in[8];
    const float* bc    = (const float*)d_in[9];
    const float* Wcls  = (const float*)d_in[10];
    const float* bcls  = (const float*)d_in[11];
    float* out = (float*)d_out;

    cudaFuncSetAttribute(k_recur, cudaFuncAttributeMaxDynamicSharedMemorySize, SMEM_BYTES);

    k_prep<<<VV + 224, 512>>>(emb, Wf, Wi, Wo, Wc, bf, bi, bo, bc);
    k_recur<<<BB / 2, 256, SMEM_BYTES>>>(reviews, Wcls, bcls, out);
}